// round 13
// baseline (speedup 1.0000x reference)
#include <cuda_runtime.h>
#include <cuda_fp16.h>
#include <cstdint>

// Problem constants
#define B_  2
#define T_  2048
#define C_  1024
#define H_  16
#define HD_ 64
#define NR  (B_*T_)          // 4096 rows
#define FF  (4*C_)           // 4096
#define QSCALE 0.18033688f   // 0.125 * log2(e), folded into q

// ---------------- scratch (no allocations allowed) ----------------
__device__ __half g_h  [NR*C_];   // ln1 out (fp16)
__device__ __half g_q  [NR*C_];   // pre-scaled by QSCALE
__device__ __half g_k  [NR*C_];
__device__ __half g_v  [NR*C_];
__device__ __half g_att[NR*C_];
__device__ float  g_x2 [NR*C_];   // post-attention residual (fp32)
__device__ __half g_h2 [NR*C_];
__device__ __half g_ff1[NR*FF];
// fp16, TRANSPOSED weight copies ([N][K] layout)
__device__ __half g_wq [C_*C_];
__device__ __half g_wk [C_*C_];
__device__ __half g_wv [C_*C_];
__device__ __half g_wo [C_*C_];
__device__ __half g_w1 [C_*FF];   // [4096][1024]
__device__ __half g_w2 [FF*C_];   // [1024][4096]

// ---------------- small helpers ----------------
__device__ __forceinline__ uint32_t smem_u32(const void* p) {
    uint32_t a;
    asm("{ .reg .u64 t; cvta.to.shared.u64 t, %1; cvt.u32.u64 %0, t; }"
        : "=r"(a) : "l"(p));
    return a;
}
__device__ __forceinline__ void cp_async16(uint32_t s, const void* g) {
    asm volatile("cp.async.cg.shared.global [%0], [%1], 16;" :: "r"(s), "l"(g));
}
__device__ __forceinline__ void cp_commit() {
    asm volatile("cp.async.commit_group;");
}
__device__ __forceinline__ void cp_wait0() {
    asm volatile("cp.async.wait_group 0;");
}
__device__ __forceinline__ void cp_wait2() {
    asm volatile("cp.async.wait_group 2;");
}
__device__ __forceinline__ float ex2f(float x) {   // raw MUFU.EX2
    float r;
    asm("ex2.approx.ftz.f32 %0, %1;" : "=f"(r) : "f"(x));
    return r;
}
__device__ __forceinline__ uint32_t pack_h2(float x, float y) {
    __half2 h = __floats2half2_rn(x, y);
    return *(uint32_t*)&h;
}
__device__ __forceinline__ void ldsm_x4(uint32_t* r, uint32_t addr) {
    asm volatile("ldmatrix.sync.aligned.m8n8.x4.shared.b16 {%0,%1,%2,%3}, [%4];"
        : "=r"(r[0]), "=r"(r[1]), "=r"(r[2]), "=r"(r[3]) : "r"(addr));
}
__device__ __forceinline__ void ldsm_x4_t(uint32_t* r, uint32_t addr) {
    asm volatile("ldmatrix.sync.aligned.m8n8.x4.trans.shared.b16 {%0,%1,%2,%3}, [%4];"
        : "=r"(r[0]), "=r"(r[1]), "=r"(r[2]), "=r"(r[3]) : "r"(addr));
}
__device__ __forceinline__ void mma_f16(float* acc, const uint32_t* a,
                                        uint32_t b0, uint32_t b1) {
    asm volatile(
        "mma.sync.aligned.m16n8k16.row.col.f32.f16.f16.f32 "
        "{%0,%1,%2,%3},{%4,%5,%6,%7},{%8,%9},{%0,%1,%2,%3};"
        : "+f"(acc[0]), "+f"(acc[1]), "+f"(acc[2]), "+f"(acc[3])
        : "r"(a[0]), "r"(a[1]), "r"(a[2]), "r"(a[3]), "r"(b0), "r"(b1));
}

// -------- fused fp16-convert + transpose of all weights: W[K,N]->Wt[N,K] ---
__global__ void cvt_t_kernel(const float* __restrict__ Wq, const float* __restrict__ Wk,
                             const float* __restrict__ Wv, const float* __restrict__ Wo,
                             const float* __restrict__ W1, const float* __restrict__ W2,
                             __half* __restrict__ wq, __half* __restrict__ wk,
                             __half* __restrict__ wv, __half* __restrict__ wo,
                             __half* __restrict__ w1, __half* __restrict__ w2) {
    __shared__ float tile[32][33];
    int bid = blockIdx.x;
    const float* S; __half* D; int K, N, t;
    if (bid < 4096) {
        int r = bid >> 10; t = bid & 1023; K = 1024; N = 1024;
        S = r == 0 ? Wq : r == 1 ? Wk : r == 2 ? Wv : Wo;
        D = r == 0 ? wq : r == 1 ? wk : r == 2 ? wv : wo;
    } else if (bid < 8192) {
        t = bid - 4096; K = 1024; N = 4096; S = W1; D = w1;
    } else {
        t = bid - 8192; K = 4096; N = 1024; S = W2; D = w2;
    }
    int tnc = N >> 5;
    int tk = (t / tnc) << 5;
    int tn = (t % tnc) << 5;
    int c  = threadIdx.x & 31, r8 = threadIdx.x >> 5;
    #pragma unroll
    for (int i = 0; i < 4; i++) {
        int kk = tk + r8 + i * 8;
        tile[r8 + i * 8][c] = S[(size_t)kk * N + tn + c];
    }
    __syncthreads();
    #pragma unroll
    for (int i = 0; i < 4; i++) {
        int nn = tn + r8 + i * 8;
        D[(size_t)nn * K + tk + c] = __float2half_rn(tile[c][r8 + i * 8]);
    }
}

// ---------------- block reduction (256 threads) ----------------
__device__ __forceinline__ float block_sum256(float v) {
    __shared__ float red[8];
    #pragma unroll
    for (int o = 16; o; o >>= 1) v += __shfl_xor_sync(0xffffffffu, v, o);
    __syncthreads();
    if ((threadIdx.x & 31) == 0) red[threadIdx.x >> 5] = v;
    __syncthreads();
    float s = 0.f;
    #pragma unroll
    for (int i = 0; i < 8; i++) s += red[i];
    return s;
}

// ---------------- LayerNorm: fp32 in, fp16 out ----------------
__global__ void ln_kernel(const float* __restrict__ x,
                          const float* __restrict__ g,
                          const float* __restrict__ b,
                          __half* __restrict__ out) {
    int row = blockIdx.x;
    const float4* xr = (const float4*)(x + (size_t)row * C_);
    float4 xa = xr[threadIdx.x];

    float s = xa.x + xa.y + xa.z + xa.w;
    float mu = block_sum256(s) * (1.0f / C_);

    float dx = xa.x - mu, dy = xa.y - mu, dz = xa.z - mu, dw = xa.w - mu;
    float sq = dx*dx + dy*dy + dz*dz + dw*dw;
    float var = block_sum256(sq) * (1.0f / C_);
    float rstd = rsqrtf(var + 1e-5f);

    float4 gg = ((const float4*)g)[threadIdx.x];
    float4 bb = ((const float4*)b)[threadIdx.x];
    __half2* od = (__half2*)(out + (size_t)row * C_);
    od[2 * threadIdx.x    ] = __floats2half2_rn(dx * rstd * gg.x + bb.x,
                                                dy * rstd * gg.y + bb.y);
    od[2 * threadIdx.x + 1] = __floats2half2_rn(dz * rstd * gg.z + bb.z,
                                                dw * rstd * gg.w + bb.w);
}

// ============ fp16 tensor-core GEMM: C = A[M,K] @ Bt[N,K]^T ===============
// BM=128, BN=128, BK=32; 256 threads = 8 warps (2 m-slots x 4 n-slots);
// warp tile 64x32 -> acc 64 regs/thread, 4 warps/SMSP at 2 CTAs/SM.
// A and B both K-major stride-40 smem; all ldmatrix non-trans.
// Per warp per k-tile: 12 LDSM + 32 MMA (A shared by 4 n-slot warps).
// 4 cp.async stages, one barrier per k-tile.
// EPI: 0 none (half out, optional oscale), 1 bias+relu (half out),
//      2 bias+residual (float out)
#define GEMM_SMEM_BYTES (4 * 20480)

template <int EPI>
__device__ __forceinline__ void gemm_h_body(
        const __half* __restrict__ A, const __half* __restrict__ Bt,
        const float* __restrict__ bias, const float* __restrict__ res,
        void* __restrict__ Cm, int M, int N, int K, int bx, int by,
        float oscale) {
    extern __shared__ char smraw[];
    const uint32_t sb = smem_u32(smraw);

    const int tx   = threadIdx.x;          // 0..255
    const int warp = tx >> 5;              // 0..7
    const int lane = tx & 31;
    const int g    = lane >> 2;
    const int t    = lane & 3;
    const int wr   = (warp >> 2) * 64;     // m-slot: 0/64
    const int wc   = (warp & 3) * 32;      // n-slot: 0/32/64/96
    const int brow = by * 128;
    const int bcol = bx * 128;

    // ldmatrix per-lane offsets (bytes), stride 40 halves = 80B
    const int a_row = lane & 15;
    const int a_k8  = (lane >> 4) * 8;
    const int b_n   = (lane & 7) + (lane >> 4) * 8;
    const int b_k8  = ((lane >> 3) & 1) * 8;
    const uint32_t aoff = ((wr + a_row) * 40 + a_k8) * 2;
    const uint32_t boff = ((wc + b_n)   * 40 + b_k8) * 2;

    float acc[4][4][4];                    // 4 mtiles x 4 ntiles
    #pragma unroll
    for (int mt = 0; mt < 4; mt++)
        #pragma unroll
        for (int nt = 0; nt < 4; nt++)
            #pragma unroll
            for (int i = 0; i < 4; i++) acc[mt][nt][i] = 0.f;

    const int ntiles = K >> 5;
    auto load_tile = [&](int kt, int s) {
        if (kt < ntiles) {
            uint32_t ab = sb + s * 20480;
            uint32_t bb2 = ab + 10240;
            const __half* ag = A  + (size_t)brow * K + kt * 32;
            const __half* bg = Bt + (size_t)bcol * K + kt * 32;
            #pragma unroll
            for (int i = 0; i < 2; i++) {
                int f = tx + 256 * i, row = f >> 2, ch = f & 3;
                uint32_t d = row * 80 + ch * 16;
                cp_async16(ab + d,  ag + (size_t)row * K + ch * 8);
                cp_async16(bb2 + d, bg + (size_t)row * K + ch * 8);
            }
        }
        cp_commit();   // always commit to keep wait counts aligned
    };

    load_tile(0, 0);
    load_tile(1, 1);
    load_tile(2, 2);

    int s_c = 0, s_w = 3;
    for (int kt = 0; kt < ntiles; kt++) {
        cp_wait2();        // tile kt landed (<=2 younger groups in flight)
        __syncthreads();
        load_tile(kt + 3, s_w);

        const uint32_t ab = sb + s_c * 20480;
        const uint32_t bb2 = ab + 10240;

        #pragma unroll
        for (int ks = 0; ks < 2; ks++) {
            uint32_t a[4][4], bq[2][4];
            #pragma unroll
            for (int mt = 0; mt < 4; mt++)
                ldsm_x4(a[mt], ab + aoff + mt * 1280 + ks * 32);
            #pragma unroll
            for (int nt2 = 0; nt2 < 2; nt2++)
                ldsm_x4(bq[nt2], bb2 + boff + nt2 * 1280 + ks * 32);
            #pragma unroll
            for (int mt = 0; mt < 4; mt++)
                #pragma unroll
                for (int nt = 0; nt < 4; nt++)
                    mma_f16(acc[mt][nt], a[mt],
                            bq[nt >> 1][(nt & 1) * 2],
                            bq[nt >> 1][(nt & 1) * 2 + 1]);
        }
        s_c = (s_c + 1) & 3;
        s_w = (s_w + 1) & 3;
    }

    // epilogue: c0=(g,2t) c1=(g,2t+1) c2=(g+8,2t) c3=(g+8,2t+1)
    #pragma unroll
    for (int mt = 0; mt < 4; mt++) {
        #pragma unroll
        for (int hh = 0; hh < 2; hh++) {
            int row = brow + wr + mt * 16 + g + hh * 8;
            #pragma unroll
            for (int nt = 0; nt < 4; nt++) {
                int col = bcol + wc + nt * 8 + 2 * t;
                float ox = acc[mt][nt][hh * 2 + 0];
                float oy = acc[mt][nt][hh * 2 + 1];
                if (EPI >= 1) { ox += bias[col]; oy += bias[col + 1]; }
                if (EPI == 1) { ox = fmaxf(ox, 0.f); oy = fmaxf(oy, 0.f); }
                if (EPI == 2) {
                    float2 rr = *(const float2*)(res + (size_t)row * N + col);
                    *(float2*)((float*)Cm + (size_t)row * N + col) =
                        make_float2(ox + rr.x, oy + rr.y);
                } else {
                    if (EPI == 0) { ox *= oscale; oy *= oscale; }
                    *(__half2*)((__half*)Cm + (size_t)row * N + col) =
                        __floats2half2_rn(ox, oy);
                }
            }
        }
    }
}

template <int EPI>
__global__ void __launch_bounds__(256, 2)
gemm_h(const __half* __restrict__ A, const __half* __restrict__ Bt,
       const float* __restrict__ bias, const float* __restrict__ res,
       void* __restrict__ Cm, int M, int N, int K) {
    gemm_h_body<EPI>(A, Bt, bias, res, Cm, M, N, K, blockIdx.x, blockIdx.y, 1.0f);
}

__global__ void __launch_bounds__(256, 2)
gemm_h_qkv(const __half* __restrict__ A,
           const __half* __restrict__ W0, const __half* __restrict__ W1,
           const __half* __restrict__ W2,
           __half* __restrict__ C0, __half* __restrict__ C1,
           __half* __restrict__ C2, int M, int N, int K) {
    const __half* W = (blockIdx.z == 0) ? W0 : (blockIdx.z == 1) ? W1 : W2;
    __half*      Cc = (blockIdx.z == 0) ? C0 : (blockIdx.z == 1) ? C1 : C2;
    float sc = (blockIdx.z == 0) ? QSCALE : 1.0f;
    gemm_h_body<0>(A, W, nullptr, nullptr, Cc, M, N, K, blockIdx.x, blockIdx.y, sc);
}

// ============ fp16 flash attention: register-resident P (FA2 style) =======
// grid: (T/64 q-tiles reversed, B*H). block: 128 threads = 4 warps.
// Br=Bc=64, HD=64. Warp tile 16 rows x 64 keys. Row stride 72 halves (144B).
// q pre-scaled by 0.125*log2e -> p = 2^(S - m) via MUFU.EX2.
// P stays in registers (C-frag == A-frag). One __syncthreads per key tile.
#define KSOFF(s) (9216 + (s) * 9216)
#define VSOFF(s) (27648 + (s) * 9216)
#define ATT_SMEM_BYTES 46080

__global__ void __launch_bounds__(128, 4)
attn_h_kernel(const __half* __restrict__ q,
              const __half* __restrict__ k,
              const __half* __restrict__ v,
              __half* __restrict__ o) {
    extern __shared__ char smraw[];
    const uint32_t sb = smem_u32(smraw);

    const int tx   = threadIdx.x;
    const int w    = tx >> 5;
    const int lane = tx & 31;
    const int g    = lane >> 2;
    const int t    = lane & 3;
    const int bh   = blockIdx.y;
    const int b    = bh >> 4;
    const int h    = bh & 15;
    const int qt   = gridDim.x - 1 - blockIdx.x;   // big tiles first
    const int t0   = qt * 64;
    const size_t base = (size_t)b * T_ * C_ + (size_t)h * HD_;

    // ldmatrix per-lane offsets (stride 72 halves = 144B)
    const int a_row = lane & 15;
    const int a_k8  = (lane >> 4) * 8;
    const int b_n   = (lane & 7) + (lane >> 4) * 8;
    const int b_k8  = ((lane >> 3) & 1) * 8;
    const int v_k   = (lane & 7) + ((lane >> 3) & 1) * 8;
    const int v_c   = (lane >> 4) * 8;
    const uint32_t qoff = ((w * 16 + a_row) * 72 + a_k8) * 2;

    // prologue: Q + K0 + V0
    #pragma unroll
    for (int i = 0; i < 4; i++) {
        int f = tx + 128 * i, row = f >> 3, ch = f & 7;
        uint32_t d = row * 144 + ch * 16;
        cp_async16(sb + d,            q + base + (size_t)(t0 + row) * C_ + ch * 8);
        cp_async16(sb + KSOFF(0) + d, k + base + (size_t)row * C_ + ch * 8);
        cp_async16(sb + VSOFF(0) + d, v + base + (size_t)row * C_ + ch * 8);
    }
    cp_commit();

    float acc_o[8][4];
    #pragma unroll
    for (int nt = 0; nt < 8; nt++)
        #pragma unroll
        for (int i = 0; i < 4; i++) acc_o[nt][i] = 0.f;
    float mrow[2] = {-1e30f, -1e30f};
    float lrow[2] = {0.f, 0.f};

    int buf = 0;
    for (int j = 0; j <= qt; j++) {
        cp_wait0();
        __syncthreads();   // data j ready; all warps fully done with iter j-1

        if (j < qt) {
            const __half* kg = k + base + (size_t)(j + 1) * 64 * C_;
            const __half* vg = v + base + (size_t)(j + 1) * 64 * C_;
            #pragma unroll
            for (int i = 0; i < 4; i++) {
                int f = tx + 128 * i, row = f >> 3, ch = f & 7;
                uint32_t d = row * 144 + ch * 16;
                cp_async16(sb + KSOFF(buf ^ 1) + d, kg + (size_t)row * C_ + ch * 8);
                cp_async16(sb + VSOFF(buf ^ 1) + d, vg + (size_t)row * C_ + ch * 8);
            }
            cp_commit();
        }

        // ---- S = Q @ K^T  (softmax scale pre-folded into q) ----
        float acc_s[8][4];
        #pragma unroll
        for (int nt = 0; nt < 8; nt++)
            #pragma unroll
            for (int i = 0; i < 4; i++) acc_s[nt][i] = 0.f;

        #pragma unroll
        for (int ks = 0; ks < 4; ks++) {
            uint32_t aq[4], bk[4][4];
            ldsm_x4(aq, sb + qoff + ks * 32);
            #pragma unroll
            for (int nt2 = 0; nt2 < 4; nt2++)
                ldsm_x4(bk[nt2], sb + KSOFF(buf) +
                        ((nt2 * 16 + b_n) * 72 + ks * 16 + b_k8) * 2);
            #pragma unroll
            for (int nt = 0; nt < 8; nt++)
                mma_f16(acc_s[nt], aq,
                        bk[nt >> 1][(nt & 1) * 2],
                        bk[nt >> 1][(nt & 1) * 2 + 1]);
        }

        // ---- online softmax in log2 domain (warp-local, quad reduce) ----
        const int kt0 = j * 64;
        #pragma unroll
        for (int hh = 0; hh < 2; hh++) {
            const int rowg = t0 + w * 16 + g + hh * 8;
            float rmax = -1e30f;
            if (j == qt) {   // mask only on the diagonal tile
                #pragma unroll
                for (int nt = 0; nt < 8; nt++) {
                    if (kt0 + nt * 8 + 2 * t     > rowg) acc_s[nt][2 * hh]     = -1e30f;
                    if (kt0 + nt * 8 + 2 * t + 1 > rowg) acc_s[nt][2 * hh + 1] = -1e30f;
                }
            }
            #pragma unroll
            for (int nt = 0; nt < 8; nt++)
                rmax = fmaxf(rmax, fmaxf(acc_s[nt][2 * hh], acc_s[nt][2 * hh + 1]));
            rmax = fmaxf(rmax, __shfl_xor_sync(0xffffffffu, rmax, 1));
            rmax = fmaxf(rmax, __shfl_xor_sync(0xffffffffu, rmax, 2));
            float mnew  = fmaxf(mrow[hh], rmax);
            float alpha = ex2f(mrow[hh] - mnew);
            mrow[hh] = mnew;
            float rsum = 0.f;
            #pragma unroll
            for (int nt = 0; nt < 8; nt++) {
                float p0 = ex2f(acc_s[nt][2 * hh]     - mnew);
                float p1 = ex2f(acc_s[nt][2 * hh + 1] - mnew);
                acc_s[nt][2 * hh]     = p0;
                acc_s[nt][2 * hh + 1] = p1;
                rsum += p0 + p1;
                acc_o[nt][2 * hh]     *= alpha;
                acc_o[nt][2 * hh + 1] *= alpha;
            }
            rsum += __shfl_xor_sync(0xffffffffu, rsum, 1);
            rsum += __shfl_xor_sync(0xffffffffu, rsum, 2);
            lrow[hh] = lrow[hh] * alpha + rsum;
        }

        // ---- O += P @ V : P direct from registers (C-frag == A-frag) ----
        #pragma unroll
        for (int ks = 0; ks < 4; ks++) {
            uint32_t ap[4], bv[4][4];
            ap[0] = pack_h2(acc_s[2 * ks][0],     acc_s[2 * ks][1]);
            ap[1] = pack_h2(acc_s[2 * ks][2],     acc_s[2 * ks][3]);
            ap[2] = pack_h2(acc_s[2 * ks + 1][0], acc_s[2 * ks + 1][1]);
            ap[3] = pack_h2(acc_s[2 * ks + 1][2], acc_s[2 * ks + 1][3]);
            #pragma unroll
            for (int nt2 = 0; nt2 < 4; nt2++)
                ldsm_x4_t(bv[nt2], sb + VSOFF(buf) +
                          ((ks * 16 + v_k) * 72 + nt2 * 16 + v_c) * 2);
            #pragma unroll
            for (int nt = 0; nt < 8; nt++)
                mma_f16(acc_o[nt], ap,
                        bv[nt >> 1][(nt & 1) * 2],
                        bv[nt >> 1][(nt & 1) * 2 + 1]);
        }
        buf ^= 1;
    }

    // ---- epilogue: normalize, store fp16 ----
    #pragma unroll
    for (int hh = 0; hh < 2; hh++) {
        float inv = 1.f / lrow[hh];
        int row = t0 + w * 16 + g + hh * 8;
        #pragma unroll
        for (int nt = 0; nt < 8; nt++) {
            *(__half2*)(o + base + (size_t)row * C_ + nt * 8 + 2 * t) =
                __floats2half2_rn(acc_o[nt][2 * hh] * inv,
                                  acc_o[nt][2 * hh + 1] * inv);
        }
    }
}

// ---------------- launch ----------------
extern "C" void kernel_launch(void* const* d_in, const int* in_sizes, int n_in,
                              void* d_out, int out_size) {
    const float* x    = (const float*)d_in[0];
    const float* Wq   = (const float*)d_in[1];
    const float* Wk   = (const float*)d_in[2];
    const float* Wv   = (const float*)d_in[3];
    const float* Wo   = (const float*)d_in[4];
    const float* bo   = (const float*)d_in[5];
    const float* ln1g = (const float*)d_in[6];
    const float* ln1b = (const float*)d_in[7];
    const float* ln2g = (const float*)d_in[8];
    const float* ln2b = (const float*)d_in[9];
    const float* W1   = (const float*)d_in[10];
    const float* b1   = (const float*)d_in[11];
    const float* W2   = (const float*)d_in[12];
    const float* b2   = (const float*)d_in[13];
    float* out = (float*)d_out;

    __half *h, *q, *k, *v, *att, *h2, *ff1;
    __half *wq, *wk, *wv, *wo, *w1, *w2;
    float *x2;
    cudaGetSymbolAddress((void**)&h,   g_h);
    cudaGetSymbolAddress((void**)&q,   g_q);
    cudaGetSymbolAddress((void**)&k,   g_k);
    cudaGetSymbolAddress((void**)&v,   g_v);
    cudaGetSymbolAddress((void**)&att, g_att);
    cudaGetSymbolAddress((void**)&x2,  g_x2);
    cudaGetSymbolAddress((void**)&h2,  g_h2);
    cudaGetSymbolAddress((void**)&ff1, g_ff1);
    cudaGetSymbolAddress((void**)&wq,  g_wq);
    cudaGetSymbolAddress((void**)&wk,  g_wk);
    cudaGetSymbolAddress((void**)&wv,  g_wv);
    cudaGetSymbolAddress((void**)&wo,  g_wo);
    cudaGetSymbolAddress((void**)&w1,  g_w1);
    cudaGetSymbolAddress((void**)&w2,  g_w2);

    cudaFuncSetAttribute(gemm_h<0>, cudaFuncAttributeMaxDynamicSharedMemorySize, GEMM_SMEM_BYTES);
    cudaFuncSetAttribute(gemm_h<1>, cudaFuncAttributeMaxDynamicSharedMemorySize, GEMM_SMEM_BYTES);
    cudaFuncSetAttribute(gemm_h<2>, cudaFuncAttributeMaxDynamicSharedMemorySize, GEMM_SMEM_BYTES);
    cudaFuncSetAttribute(gemm_h_qkv, cudaFuncAttributeMaxDynamicSharedMemorySize, GEMM_SMEM_BYTES);
    cudaFuncSetAttribute(attn_h_kernel, cudaFuncAttributeMaxDynamicSharedMemorySize, ATT_SMEM_BYTES);

    // 0. convert + transpose weights -> fp16 [N][K]
    cvt_t_kernel<<<12288, 256>>>(Wq, Wk, Wv, Wo, W1, W2, wq, wk, wv, wo, w1, w2);

    // 1. h = LN1(x)  (fp16 out)
    ln_kernel<<<NR, 256>>>(x, ln1g, ln1b, h);

    // 2. q,k,v = h @ {Wq,Wk,Wv}  (fp16; q pre-scaled by QSCALE)
    gemm_h_qkv<<<dim3(C_ / 128, NR / 128, 3), 256, GEMM_SMEM_BYTES>>>(
        h, wq, wk, wv, q, k, v, NR, C_, C_);

    // 3. causal attention (fp16, exp2 softmax, register-P)
    attn_h_kernel<<<dim3(T_ / 64, B_ * H_), 128, ATT_SMEM_BYTES>>>(q, k, v, att);

    // 4. x2 = x + att @ Wo + bo  (fp32 out)
    gemm_h<2><<<dim3(C_ / 128, NR / 128), 256, GEMM_SMEM_BYTES>>>(att, wo, bo, x, x2, NR, C_, C_);

    // 5. h2 = LN2(x2)  (fp16 out)
    ln_kernel<<<NR, 256>>>(x2, ln2g, ln2b, h2);

    // 6. ff1 = relu(h2 @ W1 + b1)  (fp16 out)
    gemm_h<1><<<dim3(FF / 128, NR / 128), 256, GEMM_SMEM_BYTES>>>(h2, w1, b1, nullptr, ff1, NR, FF, C_);

    // 7. out = x2 + ff1 @ W2 + b2  (fp32 out)
    gemm_h<2><<<dim3(C_ / 128, NR / 128), 256, GEMM_SMEM_BYTES>>>(ff1, w2, b2, x2, out, NR, C_, FF);
}

// round 14
// speedup vs baseline: 1.0909x; 1.0909x over previous
#include <cuda_runtime.h>
#include <cuda_fp16.h>
#include <cstdint>

// Problem constants
#define B_  2
#define T_  2048
#define C_  1024
#define H_  16
#define HD_ 64
#define NR  (B_*T_)          // 4096 rows
#define FF  (4*C_)           // 4096
#define QSCALE 0.18033688f   // 0.125 * log2(e), folded into q

// ---------------- scratch (no allocations allowed) ----------------
__device__ __half g_h  [NR*C_];   // ln1 out (fp16)
__device__ __half g_q  [NR*C_];   // pre-scaled by QSCALE
__device__ __half g_k  [NR*C_];
__device__ __half g_v  [NR*C_];
__device__ __half g_att[NR*C_];
__device__ float  g_x2 [NR*C_];   // post-attention residual (fp32)
__device__ __half g_h2 [NR*C_];
__device__ __half g_ff1[NR*FF];
// fp16, TRANSPOSED weight copies ([N][K] layout)
__device__ __half g_wq [C_*C_];
__device__ __half g_wk [C_*C_];
__device__ __half g_wv [C_*C_];
__device__ __half g_wo [C_*C_];
__device__ __half g_w1 [C_*FF];   // [4096][1024]
__device__ __half g_w2 [FF*C_];   // [1024][4096]

// ---------------- small helpers ----------------
__device__ __forceinline__ uint32_t smem_u32(const void* p) {
    uint32_t a;
    asm("{ .reg .u64 t; cvta.to.shared.u64 t, %1; cvt.u32.u64 %0, t; }"
        : "=r"(a) : "l"(p));
    return a;
}
__device__ __forceinline__ void cp_async16(uint32_t s, const void* g) {
    asm volatile("cp.async.cg.shared.global [%0], [%1], 16;" :: "r"(s), "l"(g));
}
__device__ __forceinline__ void cp_commit() {
    asm volatile("cp.async.commit_group;");
}
__device__ __forceinline__ void cp_wait0() {
    asm volatile("cp.async.wait_group 0;");
}
__device__ __forceinline__ void cp_wait2() {
    asm volatile("cp.async.wait_group 2;");
}
__device__ __forceinline__ float ex2f(float x) {   // raw MUFU.EX2
    float r;
    asm("ex2.approx.ftz.f32 %0, %1;" : "=f"(r) : "f"(x));
    return r;
}
__device__ __forceinline__ uint32_t pack_h2(float x, float y) {
    __half2 h = __floats2half2_rn(x, y);
    return *(uint32_t*)&h;
}
__device__ __forceinline__ void ldsm_x4(uint32_t* r, uint32_t addr) {
    asm volatile("ldmatrix.sync.aligned.m8n8.x4.shared.b16 {%0,%1,%2,%3}, [%4];"
        : "=r"(r[0]), "=r"(r[1]), "=r"(r[2]), "=r"(r[3]) : "r"(addr));
}
__device__ __forceinline__ void ldsm_x4_t(uint32_t* r, uint32_t addr) {
    asm volatile("ldmatrix.sync.aligned.m8n8.x4.trans.shared.b16 {%0,%1,%2,%3}, [%4];"
        : "=r"(r[0]), "=r"(r[1]), "=r"(r[2]), "=r"(r[3]) : "r"(addr));
}
__device__ __forceinline__ void mma_f16(float* acc, const uint32_t* a,
                                        uint32_t b0, uint32_t b1) {
    asm volatile(
        "mma.sync.aligned.m16n8k16.row.col.f32.f16.f16.f32 "
        "{%0,%1,%2,%3},{%4,%5,%6,%7},{%8,%9},{%0,%1,%2,%3};"
        : "+f"(acc[0]), "+f"(acc[1]), "+f"(acc[2]), "+f"(acc[3])
        : "r"(a[0]), "r"(a[1]), "r"(a[2]), "r"(a[3]), "r"(b0), "r"(b1));
}

// -------- fused fp16-convert + transpose of all weights: W[K,N]->Wt[N,K] ---
__global__ void cvt_t_kernel(const float* __restrict__ Wq, const float* __restrict__ Wk,
                             const float* __restrict__ Wv, const float* __restrict__ Wo,
                             const float* __restrict__ W1, const float* __restrict__ W2,
                             __half* __restrict__ wq, __half* __restrict__ wk,
                             __half* __restrict__ wv, __half* __restrict__ wo,
                             __half* __restrict__ w1, __half* __restrict__ w2) {
    __shared__ float tile[32][33];
    int bid = blockIdx.x;
    const float* S; __half* D; int K, N, t;
    if (bid < 4096) {
        int r = bid >> 10; t = bid & 1023; K = 1024; N = 1024;
        S = r == 0 ? Wq : r == 1 ? Wk : r == 2 ? Wv : Wo;
        D = r == 0 ? wq : r == 1 ? wk : r == 2 ? wv : wo;
    } else if (bid < 8192) {
        t = bid - 4096; K = 1024; N = 4096; S = W1; D = w1;
    } else {
        t = bid - 8192; K = 4096; N = 1024; S = W2; D = w2;
    }
    int tnc = N >> 5;
    int tk = (t / tnc) << 5;
    int tn = (t % tnc) << 5;
    int c  = threadIdx.x & 31, r8 = threadIdx.x >> 5;
    #pragma unroll
    for (int i = 0; i < 4; i++) {
        int kk = tk + r8 + i * 8;
        tile[r8 + i * 8][c] = S[(size_t)kk * N + tn + c];
    }
    __syncthreads();
    #pragma unroll
    for (int i = 0; i < 4; i++) {
        int nn = tn + r8 + i * 8;
        D[(size_t)nn * K + tk + c] = __float2half_rn(tile[c][r8 + i * 8]);
    }
}

// ---------------- block reduction (256 threads) ----------------
__device__ __forceinline__ float block_sum256(float v) {
    __shared__ float red[8];
    #pragma unroll
    for (int o = 16; o; o >>= 1) v += __shfl_xor_sync(0xffffffffu, v, o);
    __syncthreads();
    if ((threadIdx.x & 31) == 0) red[threadIdx.x >> 5] = v;
    __syncthreads();
    float s = 0.f;
    #pragma unroll
    for (int i = 0; i < 8; i++) s += red[i];
    return s;
}

// ---------------- LayerNorm: fp32 in, fp16 out ----------------
__global__ void ln_kernel(const float* __restrict__ x,
                          const float* __restrict__ g,
                          const float* __restrict__ b,
                          __half* __restrict__ out) {
    int row = blockIdx.x;
    const float4* xr = (const float4*)(x + (size_t)row * C_);
    float4 xa = xr[threadIdx.x];

    float s = xa.x + xa.y + xa.z + xa.w;
    float mu = block_sum256(s) * (1.0f / C_);

    float dx = xa.x - mu, dy = xa.y - mu, dz = xa.z - mu, dw = xa.w - mu;
    float sq = dx*dx + dy*dy + dz*dz + dw*dw;
    float var = block_sum256(sq) * (1.0f / C_);
    float rstd = rsqrtf(var + 1e-5f);

    float4 gg = ((const float4*)g)[threadIdx.x];
    float4 bb = ((const float4*)b)[threadIdx.x];
    __half2* od = (__half2*)(out + (size_t)row * C_);
    od[2 * threadIdx.x    ] = __floats2half2_rn(dx * rstd * gg.x + bb.x,
                                                dy * rstd * gg.y + bb.y);
    od[2 * threadIdx.x + 1] = __floats2half2_rn(dz * rstd * gg.z + bb.z,
                                                dw * rstd * gg.w + bb.w);
}

// ============ fp16 tensor-core GEMM: C = A[M,K] @ Bt[N,K]^T ===============
// ROUND-12 CONFIG (proven optimum): BM=128, BN=128, BK=32; 128 threads =
// 4 warps (2x2); warp tile 64x64; whole-tile fragment preload; 4 cp.async
// stages, one barrier per k-tile. N and K are COMPILE-TIME (NN, KK) so all
// strides are immediates and the k-loop trip count is static.
// EPI: 0 none (half out, optional oscale), 1 bias+relu (half out),
//      2 bias+residual (float out)
#define GEMM_SMEM_BYTES (4 * 20480)

template <int EPI, int NN, int KK>
__device__ __forceinline__ void gemm_h_body(
        const __half* __restrict__ A, const __half* __restrict__ Bt,
        const float* __restrict__ bias, const float* __restrict__ res,
        void* __restrict__ Cm, int bx, int by, float oscale) {
    extern __shared__ char smraw[];
    const uint32_t sb = smem_u32(smraw);

    const int tx   = threadIdx.x;
    const int warp = tx >> 5;
    const int lane = tx & 31;
    const int g    = lane >> 2;
    const int t    = lane & 3;
    const int wr   = (warp >> 1) * 64;
    const int wc   = (warp & 1) * 64;
    const int brow = by * 128;
    const int bcol = bx * 128;

    const int a_row = lane & 15;
    const int a_k8  = (lane >> 4) * 8;
    const int b_n   = (lane & 7) + (lane >> 4) * 8;
    const int b_k8  = ((lane >> 3) & 1) * 8;
    const uint32_t aoff = ((wr + a_row) * 40 + a_k8) * 2;
    const uint32_t boff = ((wc + b_n)   * 40 + b_k8) * 2;

    float acc[4][8][4];
    #pragma unroll
    for (int mt = 0; mt < 4; mt++)
        #pragma unroll
        for (int nt = 0; nt < 8; nt++)
            #pragma unroll
            for (int i = 0; i < 4; i++) acc[mt][nt][i] = 0.f;

    constexpr int ntiles = KK >> 5;
    auto load_tile = [&](int kt, int s) {
        if (kt < ntiles) {
            uint32_t ab = sb + s * 20480;
            uint32_t bb2 = ab + 10240;
            const __half* ag = A  + (size_t)brow * KK + kt * 32;
            const __half* bg = Bt + (size_t)bcol * KK + kt * 32;
            #pragma unroll
            for (int i = 0; i < 4; i++) {
                int f = tx + 128 * i, row = f >> 2, ch = f & 3;
                uint32_t d = row * 80 + ch * 16;
                cp_async16(ab + d,  ag + (size_t)row * KK + ch * 8);
                cp_async16(bb2 + d, bg + (size_t)row * KK + ch * 8);
            }
        }
        cp_commit();
    };

    load_tile(0, 0);
    load_tile(1, 1);
    load_tile(2, 2);

    int s_c = 0, s_w = 3;
    for (int kt = 0; kt < ntiles; kt++) {
        cp_wait2();
        __syncthreads();
        load_tile(kt + 3, s_w);

        const uint32_t ab = sb + s_c * 20480;
        const uint32_t bb2 = ab + 10240;

        uint32_t a[2][4][4], bq[2][4][4];
        #pragma unroll
        for (int ks = 0; ks < 2; ks++) {
            #pragma unroll
            for (int mt = 0; mt < 4; mt++)
                ldsm_x4(a[ks][mt], ab + aoff + mt * 1280 + ks * 32);
            #pragma unroll
            for (int nt2 = 0; nt2 < 4; nt2++)
                ldsm_x4(bq[ks][nt2], bb2 + boff + nt2 * 1280 + ks * 32);
        }
        #pragma unroll
        for (int ks = 0; ks < 2; ks++)
            #pragma unroll
            for (int mt = 0; mt < 4; mt++)
                #pragma unroll
                for (int nt = 0; nt < 8; nt++)
                    mma_f16(acc[mt][nt], a[ks][mt],
                            bq[ks][nt >> 1][(nt & 1) * 2],
                            bq[ks][nt >> 1][(nt & 1) * 2 + 1]);

        s_c = (s_c + 1) & 3;
        s_w = (s_w + 1) & 3;
    }

    #pragma unroll
    for (int mt = 0; mt < 4; mt++) {
        #pragma unroll
        for (int hh = 0; hh < 2; hh++) {
            int row = brow + wr + mt * 16 + g + hh * 8;
            #pragma unroll
            for (int nt = 0; nt < 8; nt++) {
                int col = bcol + wc + nt * 8 + 2 * t;
                float ox = acc[mt][nt][hh * 2 + 0];
                float oy = acc[mt][nt][hh * 2 + 1];
                if (EPI >= 1) { ox += bias[col]; oy += bias[col + 1]; }
                if (EPI == 1) { ox = fmaxf(ox, 0.f); oy = fmaxf(oy, 0.f); }
                if (EPI == 2) {
                    float2 rr = *(const float2*)(res + (size_t)row * NN + col);
                    *(float2*)((float*)Cm + (size_t)row * NN + col) =
                        make_float2(ox + rr.x, oy + rr.y);
                } else {
                    if (EPI == 0) { ox *= oscale; oy *= oscale; }
                    *(__half2*)((__half*)Cm + (size_t)row * NN + col) =
                        __floats2half2_rn(ox, oy);
                }
            }
        }
    }
}

template <int EPI, int NN, int KK>
__global__ void __launch_bounds__(128, 2)
gemm_h(const __half* __restrict__ A, const __half* __restrict__ Bt,
       const float* __restrict__ bias, const float* __restrict__ res,
       void* __restrict__ Cm) {
    gemm_h_body<EPI, NN, KK>(A, Bt, bias, res, Cm, blockIdx.x, blockIdx.y, 1.0f);
}

__global__ void __launch_bounds__(128, 2)
gemm_h_qkv(const __half* __restrict__ A,
           const __half* __restrict__ W0, const __half* __restrict__ W1,
           const __half* __restrict__ W2,
           __half* __restrict__ C0, __half* __restrict__ C1,
           __half* __restrict__ C2) {
    const __half* W = (blockIdx.z == 0) ? W0 : (blockIdx.z == 1) ? W1 : W2;
    __half*      Cc = (blockIdx.z == 0) ? C0 : (blockIdx.z == 1) ? C1 : C2;
    float sc = (blockIdx.z == 0) ? QSCALE : 1.0f;
    gemm_h_body<0, C_, C_>(A, W, nullptr, nullptr, Cc, blockIdx.x, blockIdx.y, sc);
}

// ============ fp16 flash attention: register-resident P (FA2 style) =======
// grid: (T/64 q-tiles reversed, B*H). block: 128 threads = 4 warps.
// Br=Bc=64, HD=64. Warp tile 16 rows x 64 keys. Row stride 72 halves (144B).
// q pre-scaled by 0.125*log2e -> p = 2^(S - m) via MUFU.EX2.
// P stays in registers (C-frag == A-frag). One __syncthreads per key tile.
#define KSOFF(s) (9216 + (s) * 9216)
#define VSOFF(s) (27648 + (s) * 9216)
#define ATT_SMEM_BYTES 46080

__global__ void __launch_bounds__(128, 4)
attn_h_kernel(const __half* __restrict__ q,
              const __half* __restrict__ k,
              const __half* __restrict__ v,
              __half* __restrict__ o) {
    extern __shared__ char smraw[];
    const uint32_t sb = smem_u32(smraw);

    const int tx   = threadIdx.x;
    const int w    = tx >> 5;
    const int lane = tx & 31;
    const int g    = lane >> 2;
    const int t    = lane & 3;
    const int bh   = blockIdx.y;
    const int b    = bh >> 4;
    const int h    = bh & 15;
    const int qt   = gridDim.x - 1 - blockIdx.x;   // big tiles first
    const int t0   = qt * 64;
    const size_t base = (size_t)b * T_ * C_ + (size_t)h * HD_;

    const int a_row = lane & 15;
    const int a_k8  = (lane >> 4) * 8;
    const int b_n   = (lane & 7) + (lane >> 4) * 8;
    const int b_k8  = ((lane >> 3) & 1) * 8;
    const int v_k   = (lane & 7) + ((lane >> 3) & 1) * 8;
    const int v_c   = (lane >> 4) * 8;
    const uint32_t qoff = ((w * 16 + a_row) * 72 + a_k8) * 2;

    // prologue: Q + K0 + V0
    #pragma unroll
    for (int i = 0; i < 4; i++) {
        int f = tx + 128 * i, row = f >> 3, ch = f & 7;
        uint32_t d = row * 144 + ch * 16;
        cp_async16(sb + d,            q + base + (size_t)(t0 + row) * C_ + ch * 8);
        cp_async16(sb + KSOFF(0) + d, k + base + (size_t)row * C_ + ch * 8);
        cp_async16(sb + VSOFF(0) + d, v + base + (size_t)row * C_ + ch * 8);
    }
    cp_commit();

    float acc_o[8][4];
    #pragma unroll
    for (int nt = 0; nt < 8; nt++)
        #pragma unroll
        for (int i = 0; i < 4; i++) acc_o[nt][i] = 0.f;
    float mrow[2] = {-1e30f, -1e30f};
    float lrow[2] = {0.f, 0.f};

    int buf = 0;
    for (int j = 0; j <= qt; j++) {
        cp_wait0();
        __syncthreads();   // data j ready; all warps fully done with iter j-1

        if (j < qt) {
            const __half* kg = k + base + (size_t)(j + 1) * 64 * C_;
            const __half* vg = v + base + (size_t)(j + 1) * 64 * C_;
            #pragma unroll
            for (int i = 0; i < 4; i++) {
                int f = tx + 128 * i, row = f >> 3, ch = f & 7;
                uint32_t d = row * 144 + ch * 16;
                cp_async16(sb + KSOFF(buf ^ 1) + d, kg + (size_t)row * C_ + ch * 8);
                cp_async16(sb + VSOFF(buf ^ 1) + d, vg + (size_t)row * C_ + ch * 8);
            }
            cp_commit();
        }

        // ---- S = Q @ K^T  (softmax scale pre-folded into q) ----
        float acc_s[8][4];
        #pragma unroll
        for (int nt = 0; nt < 8; nt++)
            #pragma unroll
            for (int i = 0; i < 4; i++) acc_s[nt][i] = 0.f;

        #pragma unroll
        for (int ks = 0; ks < 4; ks++) {
            uint32_t aq[4], bk[4][4];
            ldsm_x4(aq, sb + qoff + ks * 32);
            #pragma unroll
            for (int nt2 = 0; nt2 < 4; nt2++)
                ldsm_x4(bk[nt2], sb + KSOFF(buf) +
                        ((nt2 * 16 + b_n) * 72 + ks * 16 + b_k8) * 2);
            #pragma unroll
            for (int nt = 0; nt < 8; nt++)
                mma_f16(acc_s[nt], aq,
                        bk[nt >> 1][(nt & 1) * 2],
                        bk[nt >> 1][(nt & 1) * 2 + 1]);
        }

        // ---- online softmax in log2 domain (warp-local, quad reduce) ----
        const int kt0 = j * 64;
        #pragma unroll
        for (int hh = 0; hh < 2; hh++) {
            const int rowg = t0 + w * 16 + g + hh * 8;
            float rmax = -1e30f;
            if (j == qt) {   // mask only on the diagonal tile
                #pragma unroll
                for (int nt = 0; nt < 8; nt++) {
                    if (kt0 + nt * 8 + 2 * t     > rowg) acc_s[nt][2 * hh]     = -1e30f;
                    if (kt0 + nt * 8 + 2 * t + 1 > rowg) acc_s[nt][2 * hh + 1] = -1e30f;
                }
            }
            #pragma unroll
            for (int nt = 0; nt < 8; nt++)
                rmax = fmaxf(rmax, fmaxf(acc_s[nt][2 * hh], acc_s[nt][2 * hh + 1]));
            rmax = fmaxf(rmax, __shfl_xor_sync(0xffffffffu, rmax, 1));
            rmax = fmaxf(rmax, __shfl_xor_sync(0xffffffffu, rmax, 2));
            float mnew  = fmaxf(mrow[hh], rmax);
            float alpha = ex2f(mrow[hh] - mnew);
            mrow[hh] = mnew;
            float rsum = 0.f;
            #pragma unroll
            for (int nt = 0; nt < 8; nt++) {
                float p0 = ex2f(acc_s[nt][2 * hh]     - mnew);
                float p1 = ex2f(acc_s[nt][2 * hh + 1] - mnew);
                acc_s[nt][2 * hh]     = p0;
                acc_s[nt][2 * hh + 1] = p1;
                rsum += p0 + p1;
                acc_o[nt][2 * hh]     *= alpha;
                acc_o[nt][2 * hh + 1] *= alpha;
            }
            rsum += __shfl_xor_sync(0xffffffffu, rsum, 1);
            rsum += __shfl_xor_sync(0xffffffffu, rsum, 2);
            lrow[hh] = lrow[hh] * alpha + rsum;
        }

        // ---- O += P @ V : P direct from registers (C-frag == A-frag) ----
        #pragma unroll
        for (int ks = 0; ks < 4; ks++) {
            uint32_t ap[4], bv[4][4];
            ap[0] = pack_h2(acc_s[2 * ks][0],     acc_s[2 * ks][1]);
            ap[1] = pack_h2(acc_s[2 * ks][2],     acc_s[2 * ks][3]);
            ap[2] = pack_h2(acc_s[2 * ks + 1][0], acc_s[2 * ks + 1][1]);
            ap[3] = pack_h2(acc_s[2 * ks + 1][2], acc_s[2 * ks + 1][3]);
            #pragma unroll
            for (int nt2 = 0; nt2 < 4; nt2++)
                ldsm_x4_t(bv[nt2], sb + VSOFF(buf) +
                          ((ks * 16 + v_k) * 72 + nt2 * 16 + v_c) * 2);
            #pragma unroll
            for (int nt = 0; nt < 8; nt++)
                mma_f16(acc_o[nt], ap,
                        bv[nt >> 1][(nt & 1) * 2],
                        bv[nt >> 1][(nt & 1) * 2 + 1]);
        }
        buf ^= 1;
    }

    // ---- epilogue: normalize, store fp16 ----
    #pragma unroll
    for (int hh = 0; hh < 2; hh++) {
        float inv = 1.f / lrow[hh];
        int row = t0 + w * 16 + g + hh * 8;
        #pragma unroll
        for (int nt = 0; nt < 8; nt++) {
            *(__half2*)(o + base + (size_t)row * C_ + nt * 8 + 2 * t) =
                __floats2half2_rn(acc_o[nt][2 * hh] * inv,
                                  acc_o[nt][2 * hh + 1] * inv);
        }
    }
}

// ---------------- launch ----------------
extern "C" void kernel_launch(void* const* d_in, const int* in_sizes, int n_in,
                              void* d_out, int out_size) {
    const float* x    = (const float*)d_in[0];
    const float* Wq   = (const float*)d_in[1];
    const float* Wk   = (const float*)d_in[2];
    const float* Wv   = (const float*)d_in[3];
    const float* Wo   = (const float*)d_in[4];
    const float* bo   = (const float*)d_in[5];
    const float* ln1g = (const float*)d_in[6];
    const float* ln1b = (const float*)d_in[7];
    const float* ln2g = (const float*)d_in[8];
    const float* ln2b = (const float*)d_in[9];
    const float* W1   = (const float*)d_in[10];
    const float* b1   = (const float*)d_in[11];
    const float* W2   = (const float*)d_in[12];
    const float* b2   = (const float*)d_in[13];
    float* out = (float*)d_out;

    __half *h, *q, *k, *v, *att, *h2, *ff1;
    __half *wq, *wk, *wv, *wo, *w1, *w2;
    float *x2;
    cudaGetSymbolAddress((void**)&h,   g_h);
    cudaGetSymbolAddress((void**)&q,   g_q);
    cudaGetSymbolAddress((void**)&k,   g_k);
    cudaGetSymbolAddress((void**)&v,   g_v);
    cudaGetSymbolAddress((void**)&att, g_att);
    cudaGetSymbolAddress((void**)&x2,  g_x2);
    cudaGetSymbolAddress((void**)&h2,  g_h2);
    cudaGetSymbolAddress((void**)&ff1, g_ff1);
    cudaGetSymbolAddress((void**)&wq,  g_wq);
    cudaGetSymbolAddress((void**)&wk,  g_wk);
    cudaGetSymbolAddress((void**)&wv,  g_wv);
    cudaGetSymbolAddress((void**)&wo,  g_wo);
    cudaGetSymbolAddress((void**)&w1,  g_w1);
    cudaGetSymbolAddress((void**)&w2,  g_w2);

    cudaFuncSetAttribute((gemm_h<0, C_, C_>),  cudaFuncAttributeMaxDynamicSharedMemorySize, GEMM_SMEM_BYTES);
    cudaFuncSetAttribute((gemm_h<1, FF, C_>),  cudaFuncAttributeMaxDynamicSharedMemorySize, GEMM_SMEM_BYTES);
    cudaFuncSetAttribute((gemm_h<2, C_, C_>),  cudaFuncAttributeMaxDynamicSharedMemorySize, GEMM_SMEM_BYTES);
    cudaFuncSetAttribute((gemm_h<2, C_, FF>),  cudaFuncAttributeMaxDynamicSharedMemorySize, GEMM_SMEM_BYTES);
    cudaFuncSetAttribute(gemm_h_qkv,           cudaFuncAttributeMaxDynamicSharedMemorySize, GEMM_SMEM_BYTES);
    cudaFuncSetAttribute(attn_h_kernel,        cudaFuncAttributeMaxDynamicSharedMemorySize, ATT_SMEM_BYTES);

    // 0. convert + transpose weights -> fp16 [N][K]
    cvt_t_kernel<<<12288, 256>>>(Wq, Wk, Wv, Wo, W1, W2, wq, wk, wv, wo, w1, w2);

    // 1. h = LN1(x)  (fp16 out)
    ln_kernel<<<NR, 256>>>(x, ln1g, ln1b, h);

    // 2. q,k,v = h @ {Wq,Wk,Wv}  (fp16; q pre-scaled by QSCALE)
    gemm_h_qkv<<<dim3(C_ / 128, NR / 128, 3), 128, GEMM_SMEM_BYTES>>>(
        h, wq, wk, wv, q, k, v);

    // 3. causal attention (fp16, exp2 softmax, register-P)
    attn_h_kernel<<<dim3(T_ / 64, B_ * H_), 128, ATT_SMEM_BYTES>>>(q, k, v, att);

    // 4. x2 = x + att @ Wo + bo  (fp32 out)
    gemm_h<2, C_, C_><<<dim3(C_ / 128, NR / 128), 128, GEMM_SMEM_BYTES>>>(att, wo, bo, x, x2);

    // 5. h2 = LN2(x2)  (fp16 out)
    ln_kernel<<<NR, 256>>>(x2, ln2g, ln2b, h2);

    // 6. ff1 = relu(h2 @ W1 + b1)  (fp16 out)
    gemm_h<1, FF, C_><<<dim3(FF / 128, NR / 128), 128, GEMM_SMEM_BYTES>>>(h2, w1, b1, nullptr, ff1);

    // 7. out = x2 + ff1 @ W2 + b2  (fp32 out)
    gemm_h<2, C_, FF><<<dim3(C_ / 128, NR / 128), 128, GEMM_SMEM_BYTES>>>(ff1, w2, b2, x2, out);
}

// round 15
// speedup vs baseline: 1.2052x; 1.1048x over previous
#include <cuda_runtime.h>
#include <cuda_fp16.h>
#include <cstdint>

// Problem constants
#define B_  2
#define T_  2048
#define C_  1024
#define H_  16
#define HD_ 64
#define NR  (B_*T_)          // 4096 rows
#define FF  (4*C_)           // 4096
#define QSCALE 0.18033688f   // 0.125 * log2(e), folded into q

// ---------------- scratch (no allocations allowed) ----------------
__device__ __half g_h  [NR*C_];   // ln1 out (fp16)
__device__ __half g_q  [NR*C_];   // pre-scaled by QSCALE
__device__ __half g_k  [NR*C_];
__device__ __half g_v  [NR*C_];
__device__ __half g_att[NR*C_];
__device__ float  g_x2 [NR*C_];   // post-attention residual (fp32)
__device__ __half g_h2 [NR*C_];
__device__ __half g_ff1[NR*FF];
// fp16, TRANSPOSED weight copies ([N][K] layout)
__device__ __half g_wq [C_*C_];
__device__ __half g_wk [C_*C_];
__device__ __half g_wv [C_*C_];
__device__ __half g_wo [C_*C_];
__device__ __half g_w1 [C_*FF];   // [4096][1024]
__device__ __half g_w2 [FF*C_];   // [1024][4096]

// ---------------- small helpers ----------------
__device__ __forceinline__ uint32_t smem_u32(const void* p) {
    uint32_t a;
    asm("{ .reg .u64 t; cvta.to.shared.u64 t, %1; cvt.u32.u64 %0, t; }"
        : "=r"(a) : "l"(p));
    return a;
}
__device__ __forceinline__ void cp_async16(uint32_t s, const void* g) {
    asm volatile("cp.async.cg.shared.global [%0], [%1], 16;" :: "r"(s), "l"(g));
}
__device__ __forceinline__ void cp_commit() {
    asm volatile("cp.async.commit_group;");
}
__device__ __forceinline__ void cp_wait0() {
    asm volatile("cp.async.wait_group 0;");
}
__device__ __forceinline__ void cp_wait2() {
    asm volatile("cp.async.wait_group 2;");
}
__device__ __forceinline__ float ex2f(float x) {   // raw MUFU.EX2
    float r;
    asm("ex2.approx.ftz.f32 %0, %1;" : "=f"(r) : "f"(x));
    return r;
}
__device__ __forceinline__ uint32_t pack_h2(float x, float y) {
    __half2 h = __floats2half2_rn(x, y);
    return *(uint32_t*)&h;
}
__device__ __forceinline__ void ldsm_x4(uint32_t* r, uint32_t addr) {
    asm volatile("ldmatrix.sync.aligned.m8n8.x4.shared.b16 {%0,%1,%2,%3}, [%4];"
        : "=r"(r[0]), "=r"(r[1]), "=r"(r[2]), "=r"(r[3]) : "r"(addr));
}
__device__ __forceinline__ void ldsm_x4_t(uint32_t* r, uint32_t addr) {
    asm volatile("ldmatrix.sync.aligned.m8n8.x4.trans.shared.b16 {%0,%1,%2,%3}, [%4];"
        : "=r"(r[0]), "=r"(r[1]), "=r"(r[2]), "=r"(r[3]) : "r"(addr));
}
__device__ __forceinline__ void mma_f16(float* acc, const uint32_t* a,
                                        uint32_t b0, uint32_t b1) {
    asm volatile(
        "mma.sync.aligned.m16n8k16.row.col.f32.f16.f16.f32 "
        "{%0,%1,%2,%3},{%4,%5,%6,%7},{%8,%9},{%0,%1,%2,%3};"
        : "+f"(acc[0]), "+f"(acc[1]), "+f"(acc[2]), "+f"(acc[3])
        : "r"(a[0]), "r"(a[1]), "r"(a[2]), "r"(a[3]), "r"(b0), "r"(b1));
}

// -------- fused fp16-convert + transpose of all weights: W[K,N]->Wt[N,K] ---
__global__ void cvt_t_kernel(const float* __restrict__ Wq, const float* __restrict__ Wk,
                             const float* __restrict__ Wv, const float* __restrict__ Wo,
                             const float* __restrict__ W1, const float* __restrict__ W2,
                             __half* __restrict__ wq, __half* __restrict__ wk,
                             __half* __restrict__ wv, __half* __restrict__ wo,
                             __half* __restrict__ w1, __half* __restrict__ w2) {
    __shared__ float tile[32][33];
    int bid = blockIdx.x;
    const float* S; __half* D; int K, N, t;
    if (bid < 4096) {
        int r = bid >> 10; t = bid & 1023; K = 1024; N = 1024;
        S = r == 0 ? Wq : r == 1 ? Wk : r == 2 ? Wv : Wo;
        D = r == 0 ? wq : r == 1 ? wk : r == 2 ? wv : wo;
    } else if (bid < 8192) {
        t = bid - 4096; K = 1024; N = 4096; S = W1; D = w1;
    } else {
        t = bid - 8192; K = 4096; N = 1024; S = W2; D = w2;
    }
    int tnc = N >> 5;
    int tk = (t / tnc) << 5;
    int tn = (t % tnc) << 5;
    int c  = threadIdx.x & 31, r8 = threadIdx.x >> 5;
    #pragma unroll
    for (int i = 0; i < 4; i++) {
        int kk = tk + r8 + i * 8;
        tile[r8 + i * 8][c] = S[(size_t)kk * N + tn + c];
    }
    __syncthreads();
    #pragma unroll
    for (int i = 0; i < 4; i++) {
        int nn = tn + r8 + i * 8;
        D[(size_t)nn * K + tk + c] = __float2half_rn(tile[c][r8 + i * 8]);
    }
}

// ---------------- block reduction (256 threads) ----------------
__device__ __forceinline__ float block_sum256(float v) {
    __shared__ float red[8];
    #pragma unroll
    for (int o = 16; o; o >>= 1) v += __shfl_xor_sync(0xffffffffu, v, o);
    __syncthreads();
    if ((threadIdx.x & 31) == 0) red[threadIdx.x >> 5] = v;
    __syncthreads();
    float s = 0.f;
    #pragma unroll
    for (int i = 0; i < 8; i++) s += red[i];
    return s;
}

// ---------------- LayerNorm: fp32 in, fp16 out ----------------
__global__ void ln_kernel(const float* __restrict__ x,
                          const float* __restrict__ g,
                          const float* __restrict__ b,
                          __half* __restrict__ out) {
    int row = blockIdx.x;
    const float4* xr = (const float4*)(x + (size_t)row * C_);
    float4 xa = xr[threadIdx.x];

    float s = xa.x + xa.y + xa.z + xa.w;
    float mu = block_sum256(s) * (1.0f / C_);

    float dx = xa.x - mu, dy = xa.y - mu, dz = xa.z - mu, dw = xa.w - mu;
    float sq = dx*dx + dy*dy + dz*dz + dw*dw;
    float var = block_sum256(sq) * (1.0f / C_);
    float rstd = rsqrtf(var + 1e-5f);

    float4 gg = ((const float4*)g)[threadIdx.x];
    float4 bb = ((const float4*)b)[threadIdx.x];
    __half2* od = (__half2*)(out + (size_t)row * C_);
    od[2 * threadIdx.x    ] = __floats2half2_rn(dx * rstd * gg.x + bb.x,
                                                dy * rstd * gg.y + bb.y);
    od[2 * threadIdx.x + 1] = __floats2half2_rn(dz * rstd * gg.z + bb.z,
                                                dw * rstd * gg.w + bb.w);
}

// ============ fp16 tensor-core GEMM: C = A[M,K] @ Bt[N,K]^T ===============
// ROUND-12 CONFIG (proven optimum): BM=128, BN=128, BK=32; 128 threads =
// 4 warps (2x2); warp tile 64x64; whole-tile fragment preload; 4 cp.async
// stages, one barrier per k-tile. Next-tile cp.async issued AFTER the
// fragment preload so it doesn't delay the critical LDSM chain.
// EPI: 0 none (half out, optional oscale), 1 bias+relu (half out),
//      2 bias+residual (float out)
#define GEMM_SMEM_BYTES (4 * 20480)

template <int EPI>
__device__ __forceinline__ void gemm_h_body(
        const __half* __restrict__ A, const __half* __restrict__ Bt,
        const float* __restrict__ bias, const float* __restrict__ res,
        void* __restrict__ Cm, int M, int N, int K, int bx, int by,
        float oscale) {
    extern __shared__ char smraw[];
    const uint32_t sb = smem_u32(smraw);

    const int tx   = threadIdx.x;
    const int warp = tx >> 5;
    const int lane = tx & 31;
    const int g    = lane >> 2;
    const int t    = lane & 3;
    const int wr   = (warp >> 1) * 64;
    const int wc   = (warp & 1) * 64;
    const int brow = by * 128;
    const int bcol = bx * 128;

    const int a_row = lane & 15;
    const int a_k8  = (lane >> 4) * 8;
    const int b_n   = (lane & 7) + (lane >> 4) * 8;
    const int b_k8  = ((lane >> 3) & 1) * 8;
    const uint32_t aoff = ((wr + a_row) * 40 + a_k8) * 2;
    const uint32_t boff = ((wc + b_n)   * 40 + b_k8) * 2;

    float acc[4][8][4];
    #pragma unroll
    for (int mt = 0; mt < 4; mt++)
        #pragma unroll
        for (int nt = 0; nt < 8; nt++)
            #pragma unroll
            for (int i = 0; i < 4; i++) acc[mt][nt][i] = 0.f;

    const int ntiles = K >> 5;
    auto load_tile = [&](int kt, int s) {
        if (kt < ntiles) {
            uint32_t ab = sb + s * 20480;
            uint32_t bb2 = ab + 10240;
            const __half* ag = A  + (size_t)brow * K + kt * 32;
            const __half* bg = Bt + (size_t)bcol * K + kt * 32;
            #pragma unroll
            for (int i = 0; i < 4; i++) {
                int f = tx + 128 * i, row = f >> 2, ch = f & 3;
                uint32_t d = row * 80 + ch * 16;
                cp_async16(ab + d,  ag + (size_t)row * K + ch * 8);
                cp_async16(bb2 + d, bg + (size_t)row * K + ch * 8);
            }
        }
        cp_commit();
    };

    load_tile(0, 0);
    load_tile(1, 1);
    load_tile(2, 2);

    int s_c = 0, s_w = 3;
    for (int kt = 0; kt < ntiles; kt++) {
        cp_wait2();
        __syncthreads();

        const uint32_t ab = sb + s_c * 20480;
        const uint32_t bb2 = ab + 10240;

        // fragment preload first (critical path), then issue next tile loads
        uint32_t a[2][4][4], bq[2][4][4];
        #pragma unroll
        for (int ks = 0; ks < 2; ks++) {
            #pragma unroll
            for (int mt = 0; mt < 4; mt++)
                ldsm_x4(a[ks][mt], ab + aoff + mt * 1280 + ks * 32);
            #pragma unroll
            for (int nt2 = 0; nt2 < 4; nt2++)
                ldsm_x4(bq[ks][nt2], bb2 + boff + nt2 * 1280 + ks * 32);
        }
        load_tile(kt + 3, s_w);

        #pragma unroll
        for (int ks = 0; ks < 2; ks++)
            #pragma unroll
            for (int mt = 0; mt < 4; mt++)
                #pragma unroll
                for (int nt = 0; nt < 8; nt++)
                    mma_f16(acc[mt][nt], a[ks][mt],
                            bq[ks][nt >> 1][(nt & 1) * 2],
                            bq[ks][nt >> 1][(nt & 1) * 2 + 1]);

        s_c = (s_c + 1) & 3;
        s_w = (s_w + 1) & 3;
    }

    #pragma unroll
    for (int mt = 0; mt < 4; mt++) {
        #pragma unroll
        for (int hh = 0; hh < 2; hh++) {
            int row = brow + wr + mt * 16 + g + hh * 8;
            #pragma unroll
            for (int nt = 0; nt < 8; nt++) {
                int col = bcol + wc + nt * 8 + 2 * t;
                float ox = acc[mt][nt][hh * 2 + 0];
                float oy = acc[mt][nt][hh * 2 + 1];
                if (EPI >= 1) { ox += bias[col]; oy += bias[col + 1]; }
                if (EPI == 1) { ox = fmaxf(ox, 0.f); oy = fmaxf(oy, 0.f); }
                if (EPI == 2) {
                    float2 rr = *(const float2*)(res + (size_t)row * N + col);
                    *(float2*)((float*)Cm + (size_t)row * N + col) =
                        make_float2(ox + rr.x, oy + rr.y);
                } else {
                    if (EPI == 0) { ox *= oscale; oy *= oscale; }
                    *(__half2*)((__half*)Cm + (size_t)row * N + col) =
                        __floats2half2_rn(ox, oy);
                }
            }
        }
    }
}

template <int EPI>
__global__ void __launch_bounds__(128, 2)
gemm_h(const __half* __restrict__ A, const __half* __restrict__ Bt,
       const float* __restrict__ bias, const float* __restrict__ res,
       void* __restrict__ Cm, int M, int N, int K) {
    gemm_h_body<EPI>(A, Bt, bias, res, Cm, M, N, K, blockIdx.x, blockIdx.y, 1.0f);
}

__global__ void __launch_bounds__(128, 2)
gemm_h_qkv(const __half* __restrict__ A,
           const __half* __restrict__ W0, const __half* __restrict__ W1,
           const __half* __restrict__ W2,
           __half* __restrict__ C0, __half* __restrict__ C1,
           __half* __restrict__ C2, int M, int N, int K) {
    const __half* W = (blockIdx.z == 0) ? W0 : (blockIdx.z == 1) ? W1 : W2;
    __half*      Cc = (blockIdx.z == 0) ? C0 : (blockIdx.z == 1) ? C1 : C2;
    float sc = (blockIdx.z == 0) ? QSCALE : 1.0f;
    gemm_h_body<0>(A, W, nullptr, nullptr, Cc, M, N, K, blockIdx.x, blockIdx.y, sc);
}

// ============ fp16 flash attention: register P + balanced q-tile pairs ====
// grid: (T/128 pairs, B*H). block: 128 threads = 4 warps.
// Each CTA processes q-tiles {NT-1-bx, bx} sequentially -> every CTA does
// exactly NT+1 key-tiles of work (perfect balance, single wave at 512 CTAs).
// Br=Bc=64, HD=64; warp tile 16 rows x 64 keys; row stride 72 halves.
// q pre-scaled by 0.125*log2e -> p = 2^(S - m) via MUFU.EX2.
// P stays in registers (C-frag == A-frag). One __syncthreads per key tile.
#define KSOFF(s) (9216 + (s) * 9216)
#define VSOFF(s) (27648 + (s) * 9216)
#define ATT_SMEM_BYTES 46080

__global__ void __launch_bounds__(128, 4)
attn_h_kernel(const __half* __restrict__ q,
              const __half* __restrict__ k,
              const __half* __restrict__ v,
              __half* __restrict__ o) {
    extern __shared__ char smraw[];
    const uint32_t sb = smem_u32(smraw);

    const int tx   = threadIdx.x;
    const int w    = tx >> 5;
    const int lane = tx & 31;
    const int g    = lane >> 2;
    const int t    = lane & 3;
    const int bh   = blockIdx.y;
    const int b    = bh >> 4;
    const int h    = bh & 15;
    const int NT   = T_ / 64;                      // 32 q-tiles per head
    const size_t base = (size_t)b * T_ * C_ + (size_t)h * HD_;

    // ldmatrix per-lane offsets (stride 72 halves = 144B)
    const int a_row = lane & 15;
    const int a_k8  = (lane >> 4) * 8;
    const int b_n   = (lane & 7) + (lane >> 4) * 8;
    const int b_k8  = ((lane >> 3) & 1) * 8;
    const int v_k   = (lane & 7) + ((lane >> 3) & 1) * 8;
    const int v_c   = (lane >> 4) * 8;
    const uint32_t qoff = ((w * 16 + a_row) * 72 + a_k8) * 2;

    #pragma unroll 1
    for (int pass = 0; pass < 2; pass++) {
        const int qt = pass ? (int)blockIdx.x : (NT - 1 - (int)blockIdx.x);
        const int t0 = qt * 64;

        // prologue: Q + K0 + V0 into stage 0
        #pragma unroll
        for (int i = 0; i < 4; i++) {
            int f = tx + 128 * i, row = f >> 3, ch = f & 7;
            uint32_t d = row * 144 + ch * 16;
            cp_async16(sb + d,            q + base + (size_t)(t0 + row) * C_ + ch * 8);
            cp_async16(sb + KSOFF(0) + d, k + base + (size_t)row * C_ + ch * 8);
            cp_async16(sb + VSOFF(0) + d, v + base + (size_t)row * C_ + ch * 8);
        }
        cp_commit();

        float acc_o[8][4];
        #pragma unroll
        for (int nt = 0; nt < 8; nt++)
            #pragma unroll
            for (int i = 0; i < 4; i++) acc_o[nt][i] = 0.f;
        float mrow[2] = {-1e30f, -1e30f};
        float lrow[2] = {0.f, 0.f};

        int buf = 0;
        for (int j = 0; j <= qt; j++) {
            cp_wait0();
            __syncthreads();   // data j ready; all warps done with iter j-1

            if (j < qt) {
                const __half* kg = k + base + (size_t)(j + 1) * 64 * C_;
                const __half* vg = v + base + (size_t)(j + 1) * 64 * C_;
                #pragma unroll
                for (int i = 0; i < 4; i++) {
                    int f = tx + 128 * i, row = f >> 3, ch = f & 7;
                    uint32_t d = row * 144 + ch * 16;
                    cp_async16(sb + KSOFF(buf ^ 1) + d, kg + (size_t)row * C_ + ch * 8);
                    cp_async16(sb + VSOFF(buf ^ 1) + d, vg + (size_t)row * C_ + ch * 8);
                }
                cp_commit();
            }

            // ---- S = Q @ K^T  (softmax scale pre-folded into q) ----
            float acc_s[8][4];
            #pragma unroll
            for (int nt = 0; nt < 8; nt++)
                #pragma unroll
                for (int i = 0; i < 4; i++) acc_s[nt][i] = 0.f;

            #pragma unroll
            for (int ks = 0; ks < 4; ks++) {
                uint32_t aq[4], bk[4][4];
                ldsm_x4(aq, sb + qoff + ks * 32);
                #pragma unroll
                for (int nt2 = 0; nt2 < 4; nt2++)
                    ldsm_x4(bk[nt2], sb + KSOFF(buf) +
                            ((nt2 * 16 + b_n) * 72 + ks * 16 + b_k8) * 2);
                #pragma unroll
                for (int nt = 0; nt < 8; nt++)
                    mma_f16(acc_s[nt], aq,
                            bk[nt >> 1][(nt & 1) * 2],
                            bk[nt >> 1][(nt & 1) * 2 + 1]);
            }

            // ---- online softmax in log2 domain (warp-local, quad reduce) --
            const int kt0 = j * 64;
            #pragma unroll
            for (int hh = 0; hh < 2; hh++) {
                const int rowg = t0 + w * 16 + g + hh * 8;
                float rmax = -1e30f;
                if (j == qt) {   // mask only on the diagonal tile
                    #pragma unroll
                    for (int nt = 0; nt < 8; nt++) {
                        if (kt0 + nt * 8 + 2 * t     > rowg) acc_s[nt][2 * hh]     = -1e30f;
                        if (kt0 + nt * 8 + 2 * t + 1 > rowg) acc_s[nt][2 * hh + 1] = -1e30f;
                    }
                }
                #pragma unroll
                for (int nt = 0; nt < 8; nt++)
                    rmax = fmaxf(rmax, fmaxf(acc_s[nt][2 * hh], acc_s[nt][2 * hh + 1]));
                rmax = fmaxf(rmax, __shfl_xor_sync(0xffffffffu, rmax, 1));
                rmax = fmaxf(rmax, __shfl_xor_sync(0xffffffffu, rmax, 2));
                float mnew  = fmaxf(mrow[hh], rmax);
                float alpha = ex2f(mrow[hh] - mnew);
                mrow[hh] = mnew;
                float rsum = 0.f;
                #pragma unroll
                for (int nt = 0; nt < 8; nt++) {
                    float p0 = ex2f(acc_s[nt][2 * hh]     - mnew);
                    float p1 = ex2f(acc_s[nt][2 * hh + 1] - mnew);
                    acc_s[nt][2 * hh]     = p0;
                    acc_s[nt][2 * hh + 1] = p1;
                    rsum += p0 + p1;
                    acc_o[nt][2 * hh]     *= alpha;
                    acc_o[nt][2 * hh + 1] *= alpha;
                }
                rsum += __shfl_xor_sync(0xffffffffu, rsum, 1);
                rsum += __shfl_xor_sync(0xffffffffu, rsum, 2);
                lrow[hh] = lrow[hh] * alpha + rsum;
            }

            // ---- O += P @ V : P direct from registers (C-frag == A-frag) --
            #pragma unroll
            for (int ks = 0; ks < 4; ks++) {
                uint32_t ap[4], bv[4][4];
                ap[0] = pack_h2(acc_s[2 * ks][0],     acc_s[2 * ks][1]);
                ap[1] = pack_h2(acc_s[2 * ks][2],     acc_s[2 * ks][3]);
                ap[2] = pack_h2(acc_s[2 * ks + 1][0], acc_s[2 * ks + 1][1]);
                ap[3] = pack_h2(acc_s[2 * ks + 1][2], acc_s[2 * ks + 1][3]);
                #pragma unroll
                for (int nt2 = 0; nt2 < 4; nt2++)
                    ldsm_x4_t(bv[nt2], sb + VSOFF(buf) +
                              ((ks * 16 + v_k) * 72 + nt2 * 16 + v_c) * 2);
                #pragma unroll
                for (int nt = 0; nt < 8; nt++)
                    mma_f16(acc_o[nt], ap,
                            bv[nt >> 1][(nt & 1) * 2],
                            bv[nt >> 1][(nt & 1) * 2 + 1]);
            }
            buf ^= 1;
        }

        // ---- epilogue: normalize, store fp16 ----
        #pragma unroll
        for (int hh = 0; hh < 2; hh++) {
            float inv = 1.f / lrow[hh];
            int row = t0 + w * 16 + g + hh * 8;
            #pragma unroll
            for (int nt = 0; nt < 8; nt++) {
                *(__half2*)(o + base + (size_t)row * C_ + nt * 8 + 2 * t) =
                    __floats2half2_rn(acc_o[nt][2 * hh] * inv,
                                      acc_o[nt][2 * hh + 1] * inv);
            }
        }
        __syncthreads();   // smem free before next pass's prologue
    }
}

// ---------------- launch ----------------
extern "C" void kernel_launch(void* const* d_in, const int* in_sizes, int n_in,
                              void* d_out, int out_size) {
    const float* x    = (const float*)d_in[0];
    const float* Wq   = (const float*)d_in[1];
    const float* Wk   = (const float*)d_in[2];
    const float* Wv   = (const float*)d_in[3];
    const float* Wo   = (const float*)d_in[4];
    const float* bo   = (const float*)d_in[5];
    const float* ln1g = (const float*)d_in[6];
    const float* ln1b = (const float*)d_in[7];
    const float* ln2g = (const float*)d_in[8];
    const float* ln2b = (const float*)d_in[9];
    const float* W1   = (const float*)d_in[10];
    const float* b1   = (const float*)d_in[11];
    const float* W2   = (const float*)d_in[12];
    const float* b2   = (const float*)d_in[13];
    float* out = (float*)d_out;

    __half *h, *q, *k, *v, *att, *h2, *ff1;
    __half *wq, *wk, *wv, *wo, *w1, *w2;
    float *x2;
    cudaGetSymbolAddress((void**)&h,   g_h);
    cudaGetSymbolAddress((void**)&q,   g_q);
    cudaGetSymbolAddress((void**)&k,   g_k);
    cudaGetSymbolAddress((void**)&v,   g_v);
    cudaGetSymbolAddress((void**)&att, g_att);
    cudaGetSymbolAddress((void**)&x2,  g_x2);
    cudaGetSymbolAddress((void**)&h2,  g_h2);
    cudaGetSymbolAddress((void**)&ff1, g_ff1);
    cudaGetSymbolAddress((void**)&wq,  g_wq);
    cudaGetSymbolAddress((void**)&wk,  g_wk);
    cudaGetSymbolAddress((void**)&wv,  g_wv);
    cudaGetSymbolAddress((void**)&wo,  g_wo);
    cudaGetSymbolAddress((void**)&w1,  g_w1);
    cudaGetSymbolAddress((void**)&w2,  g_w2);

    cudaFuncSetAttribute(gemm_h<0>, cudaFuncAttributeMaxDynamicSharedMemorySize, GEMM_SMEM_BYTES);
    cudaFuncSetAttribute(gemm_h<1>, cudaFuncAttributeMaxDynamicSharedMemorySize, GEMM_SMEM_BYTES);
    cudaFuncSetAttribute(gemm_h<2>, cudaFuncAttributeMaxDynamicSharedMemorySize, GEMM_SMEM_BYTES);
    cudaFuncSetAttribute(gemm_h_qkv, cudaFuncAttributeMaxDynamicSharedMemorySize, GEMM_SMEM_BYTES);
    cudaFuncSetAttribute(attn_h_kernel, cudaFuncAttributeMaxDynamicSharedMemorySize, ATT_SMEM_BYTES);

    // 0. convert + transpose weights -> fp16 [N][K]
    cvt_t_kernel<<<12288, 256>>>(Wq, Wk, Wv, Wo, W1, W2, wq, wk, wv, wo, w1, w2);

    // 1. h = LN1(x)  (fp16 out)
    ln_kernel<<<NR, 256>>>(x, ln1g, ln1b, h);

    // 2. q,k,v = h @ {Wq,Wk,Wv}  (fp16; q pre-scaled by QSCALE)
    gemm_h_qkv<<<dim3(C_ / 128, NR / 128, 3), 128, GEMM_SMEM_BYTES>>>(
        h, wq, wk, wv, q, k, v, NR, C_, C_);

    // 3. causal attention (fp16, exp2 softmax, register-P, balanced pairs)
    attn_h_kernel<<<dim3(T_ / 128, B_ * H_), 128, ATT_SMEM_BYTES>>>(q, k, v, att);

    // 4. x2 = x + att @ Wo + bo  (fp32 out)
    gemm_h<2><<<dim3(C_ / 128, NR / 128), 128, GEMM_SMEM_BYTES>>>(att, wo, bo, x, x2, NR, C_, C_);

    // 5. h2 = LN2(x2)  (fp16 out)
    ln_kernel<<<NR, 256>>>(x2, ln2g, ln2b, h2);

    // 6. ff1 = relu(h2 @ W1 + b1)  (fp16 out)
    gemm_h<1><<<dim3(FF / 128, NR / 128), 128, GEMM_SMEM_BYTES>>>(h2, w1, b1, nullptr, ff1, NR, FF, C_);

    // 7. out = x2 + ff1 @ W2 + b2  (fp32 out)
    gemm_h<2><<<dim3(C_ / 128, NR / 128), 128, GEMM_SMEM_BYTES>>>(ff1, w2, b2, x2, out, NR, C_, FF);
}